// round 1
// baseline (speedup 1.0000x reference)
#include <cuda_runtime.h>
#include <cstdint>

#define NB 8
#define NC 64
#define NH 256
#define NW 512
#define NK 9
#define BHW (NB * NH * NW)          // 1,048,576
#define W4 (NW / 4)                 // 128

// Scratch: P[k][b][y][x] = sum_c W[c,k] * F[b,c,y,x]   (37.75 MB, static device alloc)
__device__ float g_P[(size_t)NK * BHW];

// Packed f32x2 FMA (sm_100+): d = a*b + c on two lanes at once.
#define FMA_F32X2(d, a, b, c) \
    asm("fma.rn.f32x2 %0, %1, %2, %3;" : "=l"(d) : "l"(a), "l"(b), "l"(c))

// ---------------------------------------------------------------------------
// Pass 1: channel reduction. Each thread owns 4 consecutive x for one (b,y),
// loops c=0..63, accumulating 9 tap-planes in registers (f32x2 pairs).
// ---------------------------------------------------------------------------
__global__ void __launch_bounds__(256) pass1_kernel(
    const float* __restrict__ feature,   // [B, C, H, W]
    const float* __restrict__ weight)    // [1, C, 3, 3] -> [C, 9]
{
    // Duplicated weights in shared: wdup[c*9+k] = (w, w) for direct f32x2 use.
    __shared__ float2 wdup[NC * NK];
    for (int i = threadIdx.x; i < NC * NK; i += 256) {
        float wv = weight[i];
        wdup[i] = make_float2(wv, wv);
    }
    __syncthreads();

    int g = blockIdx.x * 256 + threadIdx.x;      // [0, B*H*W/4)
    if (g >= BHW / 4) return;

    int x4u = g % W4;                             // x/4
    int yb  = g / W4;                             // b*H + y

    // feature base in ulonglong2 (=float4) units
    const ulonglong2* fptr =
        (const ulonglong2*)feature + ((size_t)(yb / NH) * NC * NH + (yb % NH)) * W4 + x4u;
    const size_t cstride = (size_t)NH * W4;       // per-channel stride in float4 units

    unsigned long long acc_lo[NK], acc_hi[NK];
#pragma unroll
    for (int k = 0; k < NK; ++k) { acc_lo[k] = 0ull; acc_hi[k] = 0ull; }

#pragma unroll 4
    for (int c = 0; c < NC; ++c) {
        ulonglong2 f = fptr[(size_t)c * cstride];     // 4 floats as 2 packed f32x2
        const unsigned long long* wp =
            (const unsigned long long*)(wdup + c * NK);
#pragma unroll
        for (int k = 0; k < NK; ++k) {
            unsigned long long w = wp[k];
            FMA_F32X2(acc_lo[k], f.x, w, acc_lo[k]);
            FMA_F32X2(acc_hi[k], f.y, w, acc_hi[k]);
        }
    }

    // Store: P[k][yb][x4..x4+3]
    size_t pbase = (size_t)yb * NW + (size_t)x4u * 4;
#pragma unroll
    for (int k = 0; k < NK; ++k) {
        float2 lo = *(float2*)&acc_lo[k];
        float2 hi = *(float2*)&acc_hi[k];
        *(float4*)(g_P + (size_t)k * BHW + pbase) =
            make_float4(lo.x, lo.y, hi.x, hi.y);
    }
}

// ---------------------------------------------------------------------------
// Pass 2: tap gather + 2x2 upsample. One thread per (h,w); indices are reused
// across all 8 batches. Writes float2 pairs (two identical values) x 2 rows.
// ---------------------------------------------------------------------------
__global__ void __launch_bounds__(256) pass2_kernel(
    const int* __restrict__ gi,    // [H, W, 9]
    const int* __restrict__ gj,    // [H, W, 9]
    float* __restrict__ out)       // [B, 1, 2H, 2W]
{
    int g = blockIdx.x * 256 + threadIdx.x;      // [0, H*W)
    if (g >= NH * NW) return;
    int h = g / NW;
    int w = g % NW;
    int ib = g * NK;

    float acc[NB];
#pragma unroll
    for (int b = 0; b < NB; ++b) acc[b] = 0.0f;

#pragma unroll
    for (int k = 0; k < NK; ++k) {
        int y = gi[ib + k];
        int x = gj[ib + k];
        const float* Pk = g_P + (size_t)k * BHW + (size_t)y * NW + x;
#pragma unroll
        for (int b = 0; b < NB; ++b)
            acc[b] += Pk[(size_t)b * NH * NW];
    }

    // out viewed as float2: [B][2H][NW] (row of 2W floats = NW float2)
    float2* o2 = (float2*)out;
#pragma unroll
    for (int b = 0; b < NB; ++b) {
        float2 v = make_float2(acc[b], acc[b]);
        size_t row0 = ((size_t)b * (2 * NH) + 2 * h) * NW + w;
        o2[row0] = v;
        o2[row0 + NW] = v;
    }
}

// ---------------------------------------------------------------------------
// Launch: graph-capturable, allocation-free.
// Inputs (metadata order): feature f32, weight f32, gi i32, gj i32.
// ---------------------------------------------------------------------------
extern "C" void kernel_launch(void* const* d_in, const int* in_sizes, int n_in,
                              void* d_out, int out_size)
{
    const float* feature = (const float*)d_in[0];
    const float* weight  = (const float*)d_in[1];
    const int*   gi      = (const int*)d_in[2];
    const int*   gj      = (const int*)d_in[3];
    float*       out     = (float*)d_out;

    // Pass 1: B*H*W/4 threads = 262144 -> 1024 blocks of 256
    pass1_kernel<<<(BHW / 4 + 255) / 256, 256>>>(feature, weight);
    // Pass 2: H*W threads = 131072 -> 512 blocks of 256
    pass2_kernel<<<(NH * NW + 255) / 256, 256>>>(gi, gj, out);
}